// round 9
// baseline (speedup 1.0000x reference)
#include <cuda_runtime.h>
#include <stdint.h>

#define BB 4
#define CC 256
#define DQK 32
#define NN 4096   // H*W
#define KT 64     // keys per tile
#define NKT (NN / KT)   // 64

#define KSTR 72   // Kt hi/lo smem stride (bank: 8*tid+gid conflict-free)
#define PSTR 72   // Ps smem stride (PV A-frag bank: 8*gid+tid conflict-free)

__device__ float g_q[BB * NN * DQK];     // [b][n][d]
__device__ float g_k[BB * NN * DQK];     // [b][m][d]
__device__ float g_v[BB * NN * CC];      // [b][m][c]

__device__ __forceinline__ uint32_t f2tf32(float f) {
    uint32_t u;
    asm("cvt.rna.tf32.f32 %0, %1;" : "=r"(u) : "f"(f));
    return u;
}

__device__ __forceinline__ void mma_tf32(float d[4],
    uint32_t a0, uint32_t a1, uint32_t a2, uint32_t a3,
    uint32_t b0, uint32_t b1)
{
    asm volatile(
        "mma.sync.aligned.m16n8k8.row.col.f32.tf32.tf32.f32 "
        "{%0,%1,%2,%3},{%4,%5,%6,%7},{%8,%9},{%0,%1,%2,%3};"
        : "+f"(d[0]), "+f"(d[1]), "+f"(d[2]), "+f"(d[3])
        : "r"(a0), "r"(a1), "r"(a2), "r"(a3), "r"(b0), "r"(b1));
}

// ---------------------------------------------------------------------------
// Projection (unchanged)
// ---------------------------------------------------------------------------
__global__ __launch_bounds__(256) void proj_kernel(
    const float* __restrict__ X, const float* __restrict__ W,
    const float* __restrict__ bias, float* __restrict__ out, int dout)
{
    const int b  = blockIdx.z;
    const int n0 = blockIdx.x * 128;
    const int j0 = blockIdx.y * 32;
    const int t  = threadIdx.x;
    const int tx = t & 31;
    const int ty = t >> 5;

    __shared__ float As[32][128];
    __shared__ float Bs[32][32];

    float acc[4][4];
#pragma unroll
    for (int i = 0; i < 4; i++)
#pragma unroll
        for (int u = 0; u < 4; u++) acc[i][u] = 0.f;

    const float* Xb = X + b * CC * NN;

    for (int c0 = 0; c0 < CC; c0 += 32) {
#pragma unroll
        for (int i = 0; i < 4; i++) {
            int idx = t + 256 * i;
            int cc  = idx >> 5;
            int nn  = (idx & 31) * 4;
            float4 v = *(const float4*)(Xb + (c0 + cc) * NN + n0 + nn);
            *(float4*)&As[cc][nn] = v;
        }
        {
            int jj = t >> 3;
            int c4 = (t & 7) * 4;
            float4 wv = *(const float4*)(W + (j0 + jj) * CC + c0 + c4);
            *(float4*)&Bs[jj][c4] = wv;
        }
        __syncthreads();

#pragma unroll
        for (int cc = 0; cc < 32; cc++) {
            float4 a = *(const float4*)&As[cc][tx * 4];
            float b0 = Bs[ty * 4 + 0][cc];
            float b1 = Bs[ty * 4 + 1][cc];
            float b2 = Bs[ty * 4 + 2][cc];
            float b3 = Bs[ty * 4 + 3][cc];
            acc[0][0] += a.x * b0; acc[0][1] += a.x * b1; acc[0][2] += a.x * b2; acc[0][3] += a.x * b3;
            acc[1][0] += a.y * b0; acc[1][1] += a.y * b1; acc[1][2] += a.y * b2; acc[1][3] += a.y * b3;
            acc[2][0] += a.z * b0; acc[2][1] += a.z * b1; acc[2][2] += a.z * b2; acc[2][3] += a.z * b3;
            acc[3][0] += a.w * b0; acc[3][1] += a.w * b1; acc[3][2] += a.w * b2; acc[3][3] += a.w * b3;
        }
        __syncthreads();
    }

    float bj0 = bias[j0 + ty * 4 + 0];
    float bj1 = bias[j0 + ty * 4 + 1];
    float bj2 = bias[j0 + ty * 4 + 2];
    float bj3 = bias[j0 + ty * 4 + 3];
#pragma unroll
    for (int i = 0; i < 4; i++) {
        float4 r;
        r.x = acc[i][0] + bj0;
        r.y = acc[i][1] + bj1;
        r.z = acc[i][2] + bj2;
        r.w = acc[i][3] + bj3;
        int n = n0 + tx * 4 + i;
        *(float4*)(out + (b * NN + n) * dout + j0 + ty * 4) = r;
    }
}

// ---------------------------------------------------------------------------
// Flash attention, all-tensor:
//   S = QK^T via split-tf32 3-pass mma (qh*kh + ql*kh + qh*kl) — ~fp32 exact.
//   Q hi/lo fragments live in registers for the whole kernel.
//   P = exp(S) on C-fragments in regs, row-sum partials kept per-thread,
//   reduced once at the end. P stored tf32 to smem (STS64 pairs).
//   PV via tf32 mma, V fragments straight from gmem.
// CTA: 64 queries, 256 threads (8 warps).
//   S map : warp w -> rows ms=(w&3)*16, cols nh=(w>>2)*32 (4 n-tiles x 4 k).
//   PV map: warp w -> all 64 rows, channels cbase=w*32.
// smem: Kh0/Kl0/Kh1/Kl1[32*72] Ps0/Ps1[64*72] lsum[128]  (~72.5 KB)
// ---------------------------------------------------------------------------
#define SMEM_FLOATS (4*32*KSTR + 2*64*PSTR + 128)

__global__ __launch_bounds__(256, 2) void flash_kernel(float* __restrict__ out)
{
    extern __shared__ float sm[];
    uint32_t* Kh0  = (uint32_t*)sm;                 // [d][m] tf32-hi
    uint32_t* Kl0  = Kh0 + 32 * KSTR;               // [d][m] tf32-lo
    uint32_t* Kh1  = Kl0 + 32 * KSTR;
    uint32_t* Kl1  = Kh1 + 32 * KSTR;
    uint32_t* Ps0  = Kl1 + 32 * KSTR;               // [r][m] tf32 P
    uint32_t* Ps1  = Ps0 + 64 * PSTR;
    float*    lsum = (float*)(Ps1 + 64 * PSTR);     // [2][64] row-sum halves

    const int b    = blockIdx.y;
    const int n0   = blockIdx.x * 64;
    const int t    = threadIdx.x;
    const int w    = t >> 5;
    const int lane = t & 31;
    const int gid  = lane >> 2;
    const int tid  = lane & 3;
    // S mapping
    const int ms = (w & 3) * 16;
    const int nh = (w >> 2) * 32;
    // PV mapping
    const int cbase = w * 32;

    const float* gq_b = g_q + (size_t)b * NN * DQK;
    const float* gk_b = g_k + (size_t)b * NN * DQK;
    const float* gv_b = g_v + (size_t)b * NN * CC;
    const float* gv_w = gv_b + tid * CC + cbase + gid;   // warp V base

    // K staging indexing (2 rows x 4 d-cols per thread)
    const int km0 = t >> 3;              // 0..31
    const int km1 = km0 + 32;            // 32..63
    const int kd4 = (t & 7) * 4;

    // --- Q hi/lo fragments (resident, loop-invariant) ---
    uint32_t qhi[4][4], qlo[4][4];
    {
        const float* q0 = gq_b + (size_t)(n0 + ms + gid) * DQK;
        const float* q1 = q0 + 8 * DQK;
#pragma unroll
        for (int kk = 0; kk < 4; kk++) {
            float v0 = q0[kk * 8 + tid];
            float v1 = q1[kk * 8 + tid];
            float v2 = q0[kk * 8 + tid + 4];
            float v3 = q1[kk * 8 + tid + 4];
            qhi[kk][0] = f2tf32(v0); qlo[kk][0] = f2tf32(v0 - __uint_as_float(qhi[kk][0]));
            qhi[kk][1] = f2tf32(v1); qlo[kk][1] = f2tf32(v1 - __uint_as_float(qhi[kk][1]));
            qhi[kk][2] = f2tf32(v2); qlo[kk][2] = f2tf32(v2 - __uint_as_float(qhi[kk][2]));
            qhi[kk][3] = f2tf32(v3); qlo[kk][3] = f2tf32(v3 - __uint_as_float(qhi[kk][3]));
        }
    }

    float acc[4][4][4];
#pragma unroll
    for (int it = 0; it < 4; it++)
#pragma unroll
        for (int jt = 0; jt < 4; jt++)
#pragma unroll
            for (int u = 0; u < 4; u++) acc[it][jt][u] = 0.f;

    float lrun_lo = 0.f, lrun_hi = 0.f;

    // --- K staging: load, split hi/lo, store both planes ---
    auto stage_k = [&](const float* gk_t, uint32_t* Kh, uint32_t* Kl) {
        float4 ka = *(const float4*)(gk_t + km0 * DQK + kd4);
        float4 kb = *(const float4*)(gk_t + km1 * DQK + kd4);
        const float* va = (const float*)&ka;
        const float* vb = (const float*)&kb;
#pragma unroll
        for (int i = 0; i < 4; i++) {
            uint32_t h0 = f2tf32(va[i]);
            uint32_t l0 = f2tf32(va[i] - __uint_as_float(h0));
            uint32_t h1 = f2tf32(vb[i]);
            uint32_t l1 = f2tf32(vb[i] - __uint_as_float(h1));
            Kh[(kd4 + i) * KSTR + km0] = h0;
            Kl[(kd4 + i) * KSTR + km0] = l0;
            Kh[(kd4 + i) * KSTR + km1] = h1;
            Kl[(kd4 + i) * KSTR + km1] = l1;
        }
    };

    // --- S phase: split-tf32 mma, exp on fragments, P -> Pw ---
    auto s_phase = [&](const uint32_t* Kh, const uint32_t* Kl, uint32_t* Pw) {
        float sf[4][4];
#pragma unroll
        for (int j = 0; j < 4; j++)
#pragma unroll
            for (int u = 0; u < 4; u++) sf[j][u] = 0.f;

#pragma unroll
        for (int kk = 0; kk < 4; kk++) {
            const int rb0 = (kk * 8 + tid) * KSTR;
            const int rb1 = (kk * 8 + tid + 4) * KSTR;
#pragma unroll
            for (int j = 0; j < 4; j++) {
                const int cn = nh + 8 * j + gid;
                uint32_t bh0 = Kh[rb0 + cn];
                uint32_t bh1 = Kh[rb1 + cn];
                uint32_t bl0 = Kl[rb0 + cn];
                uint32_t bl1 = Kl[rb1 + cn];
                mma_tf32(sf[j], qhi[kk][0], qhi[kk][1], qhi[kk][2], qhi[kk][3], bh0, bh1);
                mma_tf32(sf[j], qlo[kk][0], qlo[kk][1], qlo[kk][2], qlo[kk][3], bh0, bh1);
                mma_tf32(sf[j], qhi[kk][0], qhi[kk][1], qhi[kk][2], qhi[kk][3], bl0, bl1);
            }
        }

#pragma unroll
        for (int j = 0; j < 4; j++) {
            float e0 = __expf(sf[j][0]);
            float e1 = __expf(sf[j][1]);
            float e2 = __expf(sf[j][2]);
            float e3 = __expf(sf[j][3]);
            lrun_lo += e0 + e1;
            lrun_hi += e2 + e3;
            uint2 plo, phi;
            plo.x = f2tf32(e0); plo.y = f2tf32(e1);
            phi.x = f2tf32(e2); phi.y = f2tf32(e3);
            const int cw = nh + 8 * j + 2 * tid;
            *(uint2*)&Pw[(ms + gid)     * PSTR + cw] = plo;
            *(uint2*)&Pw[(ms + gid + 8) * PSTR + cw] = phi;
        }
    };

    // Prologue
    stage_k(gk_b, Kh0, Kl0);
    __syncthreads();
    s_phase(Kh0, Kl0, Ps0);
    stage_k(gk_b + KT * DQK, Kh1, Kl1);
    __syncthreads();

    uint32_t* Pc = Ps0;  uint32_t* Pn = Ps1;
    uint32_t* Khc = Kh1; uint32_t* Klc = Kl1;   // for S(kt+1)
    uint32_t* Khw = Kh0; uint32_t* Klw = Kl0;   // write K(kt+2)

    for (int kt = 0; kt < NKT; kt++) {
        const bool more = (kt + 1 < NKT);
        const bool dok  = (kt + 2 < NKT);

        // K(kt+2): LDG now, split+STS after PV
        float4 ka, kb;
        if (dok) {
            const float* gk_t = gk_b + (size_t)(kt + 2) * KT * DQK;
            ka = *(const float4*)(gk_t + km0 * DQK + kd4);
            kb = *(const float4*)(gk_t + km1 * DQK + kd4);
        }

        // --- PV(kt): O += P V, V fragments from gmem ---
        {
            const float* vb = gv_w + (size_t)(kt * KT) * CC;
#pragma unroll
            for (int ks = 0; ks < 8; ks++) {
                const float* vp = vb + ks * 8 * CC;
                uint32_t b0[4], b1[4];
#pragma unroll
                for (int jt = 0; jt < 4; jt++) {
                    b0[jt] = f2tf32(vp[jt * 8]);
                    b1[jt] = f2tf32(vp[4 * CC + jt * 8]);
                }
                const int m0 = ks * 8;
#pragma unroll
                for (int it = 0; it < 4; it++) {
                    uint32_t a0 = Pc[(it * 16 + gid)     * PSTR + m0 + tid];
                    uint32_t a1 = Pc[(it * 16 + gid + 8) * PSTR + m0 + tid];
                    uint32_t a2 = Pc[(it * 16 + gid)     * PSTR + m0 + tid + 4];
                    uint32_t a3 = Pc[(it * 16 + gid + 8) * PSTR + m0 + tid + 4];
#pragma unroll
                    for (int jt = 0; jt < 4; jt++)
                        mma_tf32(acc[it][jt], a0, a1, a2, a3, b0[jt], b1[jt]);
                }
            }
        }

        // Stage K(kt+2) into write buffers (no reader until after sync)
        if (dok) {
            const float* va = (const float*)&ka;
            const float* vb2 = (const float*)&kb;
#pragma unroll
            for (int i = 0; i < 4; i++) {
                uint32_t h0 = f2tf32(va[i]);
                uint32_t l0 = f2tf32(va[i] - __uint_as_float(h0));
                uint32_t h1 = f2tf32(vb2[i]);
                uint32_t l1 = f2tf32(vb2[i] - __uint_as_float(h1));
                Khw[(kd4 + i) * KSTR + km0] = h0;
                Klw[(kd4 + i) * KSTR + km0] = l0;
                Khw[(kd4 + i) * KSTR + km1] = h1;
                Klw[(kd4 + i) * KSTR + km1] = l1;
            }
        }

        // --- S(kt+1) -> Pn ---
        if (more) s_phase(Khc, Klc, Pn);
        __syncthreads();

        uint32_t* pt;
        pt = Pc;  Pc  = Pn;  Pn  = pt;
        pt = Khc; Khc = Khw; Khw = pt;
        pt = Klc; Klc = Klw; Klw = pt;
    }

    // --- final row-sum reduction (sum over tid lanes, once) ---
    lrun_lo += __shfl_xor_sync(0xffffffffu, lrun_lo, 1);
    lrun_lo += __shfl_xor_sync(0xffffffffu, lrun_lo, 2);
    lrun_hi += __shfl_xor_sync(0xffffffffu, lrun_hi, 1);
    lrun_hi += __shfl_xor_sync(0xffffffffu, lrun_hi, 2);
    if (tid == 0) {
        lsum[(w >> 2) * 64 + ms + gid]     = lrun_lo;
        lsum[(w >> 2) * 64 + ms + gid + 8] = lrun_hi;
    }
    __syncthreads();

    // --- direct STG epilogue: out[b][c][n0+r] ---
    float* ob = out + (size_t)b * CC * NN + n0;
#pragma unroll
    for (int it = 0; it < 4; it++) {
        const int r_lo = it * 16 + gid;
        const int r_hi = r_lo + 8;
        const float ilo = 1.f / (lsum[r_lo] + lsum[64 + r_lo]);
        const float ihi = 1.f / (lsum[r_hi] + lsum[64 + r_hi]);
#pragma unroll
        for (int jt = 0; jt < 4; jt++) {
            const int c0 = cbase + jt * 8 + tid * 2;
            ob[(size_t)(c0    ) * NN + r_lo] = acc[it][jt][0] * ilo;
            ob[(size_t)(c0 + 1) * NN + r_lo] = acc[it][jt][1] * ilo;
            ob[(size_t)(c0    ) * NN + r_hi] = acc[it][jt][2] * ihi;
            ob[(size_t)(c0 + 1) * NN + r_hi] = acc[it][jt][3] * ihi;
        }
    }
}

// ---------------------------------------------------------------------------
extern "C" void kernel_launch(void* const* d_in, const int* in_sizes, int n_in,
                              void* d_out, int out_size)
{
    const float* f1 = (const float*)d_in[0];
    const float* f2 = (const float*)d_in[1];
    const float* Wq = (const float*)d_in[2];
    const float* bq = (const float*)d_in[3];
    const float* Wk = (const float*)d_in[4];
    const float* bk = (const float*)d_in[5];
    const float* Wv = (const float*)d_in[6];
    const float* bv = (const float*)d_in[7];
    float* out = (float*)d_out;

    float *qp, *kp, *vp;
    cudaGetSymbolAddress((void**)&qp, g_q);
    cudaGetSymbolAddress((void**)&kp, g_k);
    cudaGetSymbolAddress((void**)&vp, g_v);

    const int smem_bytes = SMEM_FLOATS * (int)sizeof(float);
    cudaFuncSetAttribute(flash_kernel,
                         cudaFuncAttributeMaxDynamicSharedMemorySize, smem_bytes);

    proj_kernel<<<dim3(NN / 128, 1, BB), 256>>>(f1, Wq, bq, qp, DQK);
    proj_kernel<<<dim3(NN / 128, 1, BB), 256>>>(f2, Wk, bk, kp, DQK);
    proj_kernel<<<dim3(NN / 128, 8, BB), 256>>>(f2, Wv, bv, vp, CC);
    flash_kernel<<<dim3(NN / 64, BB), 256, smem_bytes>>>(out);
}

// round 10
// speedup vs baseline: 1.1035x; 1.1035x over previous
#include <cuda_runtime.h>
#include <stdint.h>

#define BB 4
#define CC 256
#define DQK 32
#define NN 4096   // H*W
#define KT 64     // keys per tile
#define NKT (NN / KT)   // 64

#define KSTR 72   // K hi/lo planes: S-phase B-frag bank = 8*tid+gid (conflict-free)
#define PSTR 68   // P plane: PV A-frag bank = 4*gid+tid (conflict-free)

__device__ float g_q[BB * NN * DQK];     // [b][n][d]
__device__ float g_k[BB * NN * DQK];     // [b][m][d]
__device__ float g_v[BB * NN * CC];      // [b][m][c]  (stored tf32-rounded)

__device__ __forceinline__ uint32_t f2tf32(float f) {
    uint32_t u;
    asm("cvt.rna.tf32.f32 %0, %1;" : "=r"(u) : "f"(f));
    return u;
}

__device__ __forceinline__ void mma_tf32(float d[4],
    uint32_t a0, uint32_t a1, uint32_t a2, uint32_t a3,
    uint32_t b0, uint32_t b1)
{
    asm volatile(
        "mma.sync.aligned.m16n8k8.row.col.f32.tf32.tf32.f32 "
        "{%0,%1,%2,%3},{%4,%5,%6,%7},{%8,%9},{%0,%1,%2,%3};"
        : "+f"(d[0]), "+f"(d[1]), "+f"(d[2]), "+f"(d[3])
        : "r"(a0), "r"(a1), "r"(a2), "r"(a3), "r"(b0), "r"(b1));
}

// ---------------------------------------------------------------------------
// Projection: out[(b*N+n)*dout + j] = bias[j] + sum_c W[j][c] * X[b][c][n]
// vtf32 != 0 -> round result to tf32 before storing (used for V).
// ---------------------------------------------------------------------------
__global__ __launch_bounds__(256) void proj_kernel(
    const float* __restrict__ X, const float* __restrict__ W,
    const float* __restrict__ bias, float* __restrict__ out, int dout,
    int vtf32)
{
    const int b  = blockIdx.z;
    const int n0 = blockIdx.x * 128;
    const int j0 = blockIdx.y * 32;
    const int t  = threadIdx.x;
    const int tx = t & 31;
    const int ty = t >> 5;

    __shared__ float As[32][128];
    __shared__ float Bs[32][32];

    float acc[4][4];
#pragma unroll
    for (int i = 0; i < 4; i++)
#pragma unroll
        for (int u = 0; u < 4; u++) acc[i][u] = 0.f;

    const float* Xb = X + b * CC * NN;

    for (int c0 = 0; c0 < CC; c0 += 32) {
#pragma unroll
        for (int i = 0; i < 4; i++) {
            int idx = t + 256 * i;
            int cc  = idx >> 5;
            int nn  = (idx & 31) * 4;
            float4 v = *(const float4*)(Xb + (c0 + cc) * NN + n0 + nn);
            *(float4*)&As[cc][nn] = v;
        }
        {
            int jj = t >> 3;
            int c4 = (t & 7) * 4;
            float4 wv = *(const float4*)(W + (j0 + jj) * CC + c0 + c4);
            *(float4*)&Bs[jj][c4] = wv;
        }
        __syncthreads();

#pragma unroll
        for (int cc = 0; cc < 32; cc++) {
            float4 a = *(const float4*)&As[cc][tx * 4];
            float b0 = Bs[ty * 4 + 0][cc];
            float b1 = Bs[ty * 4 + 1][cc];
            float b2 = Bs[ty * 4 + 2][cc];
            float b3 = Bs[ty * 4 + 3][cc];
            acc[0][0] += a.x * b0; acc[0][1] += a.x * b1; acc[0][2] += a.x * b2; acc[0][3] += a.x * b3;
            acc[1][0] += a.y * b0; acc[1][1] += a.y * b1; acc[1][2] += a.y * b2; acc[1][3] += a.y * b3;
            acc[2][0] += a.z * b0; acc[2][1] += a.z * b1; acc[2][2] += a.z * b2; acc[2][3] += a.z * b3;
            acc[3][0] += a.w * b0; acc[3][1] += a.w * b1; acc[3][2] += a.w * b2; acc[3][3] += a.w * b3;
        }
        __syncthreads();
    }

    float bj0 = bias[j0 + ty * 4 + 0];
    float bj1 = bias[j0 + ty * 4 + 1];
    float bj2 = bias[j0 + ty * 4 + 2];
    float bj3 = bias[j0 + ty * 4 + 3];
#pragma unroll
    for (int i = 0; i < 4; i++) {
        float4 r;
        r.x = acc[i][0] + bj0;
        r.y = acc[i][1] + bj1;
        r.z = acc[i][2] + bj2;
        r.w = acc[i][3] + bj3;
        if (vtf32) {
            r.x = __uint_as_float(f2tf32(r.x));
            r.y = __uint_as_float(f2tf32(r.y));
            r.z = __uint_as_float(f2tf32(r.z));
            r.w = __uint_as_float(f2tf32(r.w));
        }
        int n = n0 + tx * 4 + i;
        *(float4*)(out + (b * NN + n) * dout + j0 + ty * 4) = r;
    }
}

// ---------------------------------------------------------------------------
// Flash attention, all-tensor:
//   S = QK^T via split-tf32 3-pass mma (qh*kh + ql*kh + qh*kl) — ~fp32 exact.
//   Q hi/lo fragments resident in registers. P = exp(S) on C-fragments,
//   row-sum partials per-thread, reduced once. P stored tf32 in smem.
//   PV via tf32 mma; V fragments LDG'd from gmem (pre-rounded tf32).
// CTA: 64 queries, 256 threads (8 warps).
// smem: Kh0/Kl0/Kh1/Kl1[32*72] Ps0/Ps1[64*68] lsum[128]  (~70.5 KB)
// ---------------------------------------------------------------------------
#define SMEM_FLOATS (4*32*KSTR + 2*64*PSTR + 128)

__global__ __launch_bounds__(256, 2) void flash_kernel(float* __restrict__ out)
{
    extern __shared__ float sm[];
    uint32_t* Kh0  = (uint32_t*)sm;                 // [d][m] tf32-hi
    uint32_t* Kl0  = Kh0 + 32 * KSTR;               // [d][m] tf32-lo
    uint32_t* Kh1  = Kl0 + 32 * KSTR;
    uint32_t* Kl1  = Kh1 + 32 * KSTR;
    uint32_t* Ps0  = Kl1 + 32 * KSTR;               // [r][m] tf32 P
    uint32_t* Ps1  = Ps0 + 64 * PSTR;
    float*    lsum = (float*)(Ps1 + 64 * PSTR);     // [2][64] row-sum halves

    const int b    = blockIdx.y;
    const int n0   = blockIdx.x * 64;
    const int t    = threadIdx.x;
    const int w    = t >> 5;
    const int lane = t & 31;
    const int gid  = lane >> 2;
    const int tid  = lane & 3;
    // S mapping
    const int ms = (w & 3) * 16;
    const int nh = (w >> 2) * 32;
    // PV mapping
    const int cbase = w * 32;

    const float* gq_b = g_q + (size_t)b * NN * DQK;
    const float* gk_b = g_k + (size_t)b * NN * DQK;
    const float* gv_b = g_v + (size_t)b * NN * CC;
    const float* gv_w = gv_b + tid * CC + cbase + gid;   // warp V base

    // K staging indexing (2 rows x 4 d-cols per thread)
    const int km0 = t >> 3;              // 0..31
    const int km1 = km0 + 32;            // 32..63
    const int kd4 = (t & 7) * 4;

    // --- Q hi/lo fragments (resident, loop-invariant) ---
    uint32_t qhi[4][4], qlo[4][4];
    {
        const float* q0 = gq_b + (size_t)(n0 + ms + gid) * DQK;
        const float* q1 = q0 + 8 * DQK;
#pragma unroll
        for (int kk = 0; kk < 4; kk++) {
            float v0 = __ldg(q0 + kk * 8 + tid);
            float v1 = __ldg(q1 + kk * 8 + tid);
            float v2 = __ldg(q0 + kk * 8 + tid + 4);
            float v3 = __ldg(q1 + kk * 8 + tid + 4);
            qhi[kk][0] = f2tf32(v0); qlo[kk][0] = f2tf32(v0 - __uint_as_float(qhi[kk][0]));
            qhi[kk][1] = f2tf32(v1); qlo[kk][1] = f2tf32(v1 - __uint_as_float(qhi[kk][1]));
            qhi[kk][2] = f2tf32(v2); qlo[kk][2] = f2tf32(v2 - __uint_as_float(qhi[kk][2]));
            qhi[kk][3] = f2tf32(v3); qlo[kk][3] = f2tf32(v3 - __uint_as_float(qhi[kk][3]));
        }
    }

    float acc[4][4][4];
#pragma unroll
    for (int it = 0; it < 4; it++)
#pragma unroll
        for (int jt = 0; jt < 4; jt++)
#pragma unroll
            for (int u = 0; u < 4; u++) acc[it][jt][u] = 0.f;

    float lrun_lo = 0.f, lrun_hi = 0.f;

    // --- K staging: load, split hi/lo, store both planes ---
    auto stage_k = [&](const float* gk_t, uint32_t* Kh, uint32_t* Kl) {
        float4 ka = __ldg((const float4*)(gk_t + km0 * DQK + kd4));
        float4 kb = __ldg((const float4*)(gk_t + km1 * DQK + kd4));
        const float* va = (const float*)&ka;
        const float* vb = (const float*)&kb;
#pragma unroll
        for (int i = 0; i < 4; i++) {
            uint32_t h0 = f2tf32(va[i]);
            uint32_t l0 = f2tf32(va[i] - __uint_as_float(h0));
            uint32_t h1 = f2tf32(vb[i]);
            uint32_t l1 = f2tf32(vb[i] - __uint_as_float(h1));
            Kh[(kd4 + i) * KSTR + km0] = h0;
            Kl[(kd4 + i) * KSTR + km0] = l0;
            Kh[(kd4 + i) * KSTR + km1] = h1;
            Kl[(kd4 + i) * KSTR + km1] = l1;
        }
    };

    // --- S phase: split-tf32 mma, exp on fragments, P -> Pw ---
    auto s_phase = [&](const uint32_t* Kh, const uint32_t* Kl, uint32_t* Pw) {
        float sf[4][4];
#pragma unroll
        for (int j = 0; j < 4; j++)
#pragma unroll
            for (int u = 0; u < 4; u++) sf[j][u] = 0.f;

#pragma unroll
        for (int kk = 0; kk < 4; kk++) {
            const int rb0 = (kk * 8 + tid) * KSTR;
            const int rb1 = (kk * 8 + tid + 4) * KSTR;
#pragma unroll
            for (int j = 0; j < 4; j++) {
                const int cn = nh + 8 * j + gid;
                uint32_t bh0 = Kh[rb0 + cn];
                uint32_t bh1 = Kh[rb1 + cn];
                uint32_t bl0 = Kl[rb0 + cn];
                uint32_t bl1 = Kl[rb1 + cn];
                mma_tf32(sf[j], qhi[kk][0], qhi[kk][1], qhi[kk][2], qhi[kk][3], bh0, bh1);
                mma_tf32(sf[j], qlo[kk][0], qlo[kk][1], qlo[kk][2], qlo[kk][3], bh0, bh1);
                mma_tf32(sf[j], qhi[kk][0], qhi[kk][1], qhi[kk][2], qhi[kk][3], bl0, bl1);
            }
        }

#pragma unroll
        for (int j = 0; j < 4; j++) {
            float e0 = __expf(sf[j][0]);
            float e1 = __expf(sf[j][1]);
            float e2 = __expf(sf[j][2]);
            float e3 = __expf(sf[j][3]);
            lrun_lo += e0 + e1;
            lrun_hi += e2 + e3;
            uint2 plo, phi;
            plo.x = f2tf32(e0); plo.y = f2tf32(e1);
            phi.x = f2tf32(e2); phi.y = f2tf32(e3);
            const int cw = nh + 8 * j + 2 * tid;
            *(uint2*)&Pw[(ms + gid)     * PSTR + cw] = plo;
            *(uint2*)&Pw[(ms + gid + 8) * PSTR + cw] = phi;
        }
    };

    // Prologue
    stage_k(gk_b, Kh0, Kl0);
    __syncthreads();
    s_phase(Kh0, Kl0, Ps0);
    stage_k(gk_b + KT * DQK, Kh1, Kl1);
    __syncthreads();

    uint32_t* Pc = Ps0;  uint32_t* Pn = Ps1;
    uint32_t* Khc = Kh1; uint32_t* Klc = Kl1;   // for S(kt+1)
    uint32_t* Khw = Kh0; uint32_t* Klw = Kl0;   // write K(kt+2)

    for (int kt = 0; kt < NKT; kt++) {
        const bool more = (kt + 1 < NKT);
        const bool dok  = (kt + 2 < NKT);

        // K(kt+2): LDG now, split+STS after PV
        float4 ka, kb;
        if (dok) {
            const float* gk_t = gk_b + (size_t)(kt + 2) * KT * DQK;
            ka = __ldg((const float4*)(gk_t + km0 * DQK + kd4));
            kb = __ldg((const float4*)(gk_t + km1 * DQK + kd4));
        }

        // --- PV(kt): O += P V, V fragments from gmem (already tf32) ---
        {
            const float* vb = gv_w + (size_t)(kt * KT) * CC;
#pragma unroll
            for (int ks = 0; ks < 8; ks++) {
                const float* vp = vb + ks * 8 * CC;
                uint32_t b0[4], b1[4];
#pragma unroll
                for (int jt = 0; jt < 4; jt++) {
                    b0[jt] = __float_as_uint(__ldg(vp + jt * 8));
                    b1[jt] = __float_as_uint(__ldg(vp + 4 * CC + jt * 8));
                }
                const int m0 = ks * 8;
#pragma unroll
                for (int it = 0; it < 4; it++) {
                    uint32_t a0 = Pc[(it * 16 + gid)     * PSTR + m0 + tid];
                    uint32_t a1 = Pc[(it * 16 + gid + 8) * PSTR + m0 + tid];
                    uint32_t a2 = Pc[(it * 16 + gid)     * PSTR + m0 + tid + 4];
                    uint32_t a3 = Pc[(it * 16 + gid + 8) * PSTR + m0 + tid + 4];
#pragma unroll
                    for (int jt = 0; jt < 4; jt++)
                        mma_tf32(acc[it][jt], a0, a1, a2, a3, b0[jt], b1[jt]);
                }
            }
        }

        // Stage K(kt+2) into write buffers (no reader until after sync)
        if (dok) {
            const float* va = (const float*)&ka;
            const float* vb2 = (const float*)&kb;
#pragma unroll
            for (int i = 0; i < 4; i++) {
                uint32_t h0 = f2tf32(va[i]);
                uint32_t l0 = f2tf32(va[i] - __uint_as_float(h0));
                uint32_t h1 = f2tf32(vb2[i]);
                uint32_t l1 = f2tf32(vb2[i] - __uint_as_float(h1));
                Khw[(kd4 + i) * KSTR + km0] = h0;
                Klw[(kd4 + i) * KSTR + km0] = l0;
                Khw[(kd4 + i) * KSTR + km1] = h1;
                Klw[(kd4 + i) * KSTR + km1] = l1;
            }
        }

        // --- S(kt+1) -> Pn ---
        if (more) s_phase(Khc, Klc, Pn);
        __syncthreads();

        uint32_t* pt;
        pt = Pc;  Pc  = Pn;  Pn  = pt;
        pt = Khc; Khc = Khw; Khw = pt;
        pt = Klc; Klc = Klw; Klw = pt;
    }

    // --- final row-sum reduction (sum over tid lanes, once) ---
    lrun_lo += __shfl_xor_sync(0xffffffffu, lrun_lo, 1);
    lrun_lo += __shfl_xor_sync(0xffffffffu, lrun_lo, 2);
    lrun_hi += __shfl_xor_sync(0xffffffffu, lrun_hi, 1);
    lrun_hi += __shfl_xor_sync(0xffffffffu, lrun_hi, 2);
    if (tid == 0) {
        lsum[(w >> 2) * 64 + ms + gid]     = lrun_lo;
        lsum[(w >> 2) * 64 + ms + gid + 8] = lrun_hi;
    }
    __syncthreads();

    // --- direct STG epilogue: out[b][c][n0+r] ---
    float* ob = out + (size_t)b * CC * NN + n0;
#pragma unroll
    for (int it = 0; it < 4; it++) {
        const int r_lo = it * 16 + gid;
        const int r_hi = r_lo + 8;
        const float ilo = 1.f / (lsum[r_lo] + lsum[64 + r_lo]);
        const float ihi = 1.f / (lsum[r_hi] + lsum[64 + r_hi]);
#pragma unroll
        for (int jt = 0; jt < 4; jt++) {
            const int c0 = cbase + jt * 8 + tid * 2;
            ob[(size_t)(c0    ) * NN + r_lo] = acc[it][jt][0] * ilo;
            ob[(size_t)(c0 + 1) * NN + r_lo] = acc[it][jt][1] * ilo;
            ob[(size_t)(c0    ) * NN + r_hi] = acc[it][jt][2] * ihi;
            ob[(size_t)(c0 + 1) * NN + r_hi] = acc[it][jt][3] * ihi;
        }
    }
}

// ---------------------------------------------------------------------------
extern "C" void kernel_launch(void* const* d_in, const int* in_sizes, int n_in,
                              void* d_out, int out_size)
{
    const float* f1 = (const float*)d_in[0];
    const float* f2 = (const float*)d_in[1];
    const float* Wq = (const float*)d_in[2];
    const float* bq = (const float*)d_in[3];
    const float* Wk = (const float*)d_in[4];
    const float* bk = (const float*)d_in[5];
    const float* Wv = (const float*)d_in[6];
    const float* bv = (const float*)d_in[7];
    float* out = (float*)d_out;

    float *qp, *kp, *vp;
    cudaGetSymbolAddress((void**)&qp, g_q);
    cudaGetSymbolAddress((void**)&kp, g_k);
    cudaGetSymbolAddress((void**)&vp, g_v);

    const int smem_bytes = SMEM_FLOATS * (int)sizeof(float);
    cudaFuncSetAttribute(flash_kernel,
                         cudaFuncAttributeMaxDynamicSharedMemorySize, smem_bytes);

    proj_kernel<<<dim3(NN / 128, 1, BB), 256>>>(f1, Wq, bq, qp, DQK, 0);
    proj_kernel<<<dim3(NN / 128, 1, BB), 256>>>(f2, Wk, bk, kp, DQK, 0);
    proj_kernel<<<dim3(NN / 128, 8, BB), 256>>>(f2, Wv, bv, vp, CC, 1);
    flash_kernel<<<dim3(NN / 64, BB), 256, smem_bytes>>>(out);
}

// round 11
// speedup vs baseline: 1.1408x; 1.0338x over previous
#include <cuda_runtime.h>
#include <stdint.h>

#define BB 4
#define CC 256
#define DQK 32
#define NN 4096   // H*W
#define KT 64     // keys per tile
#define NKT (NN / KT)   // 64

#define KSTR 72    // K hi/lo planes: S-phase B-frag bank = 8*tid+gid (conflict-free)
#define PSTR 68    // P plane: PV A-frag bank = 4*gid+tid (conflict-free)
#define QLSTR 36   // qlo plane: bank = 4*gid+tid (conflict-free)

__device__ float g_q[BB * NN * DQK];     // [b][n][d]
__device__ float g_k[BB * NN * DQK];     // [b][m][d]
__device__ float g_v[BB * NN * CC];      // [b][m][c]  (stored tf32-rounded)

__device__ __forceinline__ uint32_t f2tf32(float f) {
    uint32_t u;
    asm("cvt.rna.tf32.f32 %0, %1;" : "=r"(u) : "f"(f));
    return u;
}

__device__ __forceinline__ void mma_tf32(float d[4],
    uint32_t a0, uint32_t a1, uint32_t a2, uint32_t a3,
    uint32_t b0, uint32_t b1)
{
    asm volatile(
        "mma.sync.aligned.m16n8k8.row.col.f32.tf32.tf32.f32 "
        "{%0,%1,%2,%3},{%4,%5,%6,%7},{%8,%9},{%0,%1,%2,%3};"
        : "+f"(d[0]), "+f"(d[1]), "+f"(d[2]), "+f"(d[3])
        : "r"(a0), "r"(a1), "r"(a2), "r"(a3), "r"(b0), "r"(b1));
}

// ---------------------------------------------------------------------------
// Projection: out[(b*N+n)*dout + j] = bias[j] + sum_c W[j][c] * X[b][c][n]
// vtf32 != 0 -> round result to tf32 before storing (used for V).
// ---------------------------------------------------------------------------
__global__ __launch_bounds__(256) void proj_kernel(
    const float* __restrict__ X, const float* __restrict__ W,
    const float* __restrict__ bias, float* __restrict__ out, int dout,
    int vtf32)
{
    const int b  = blockIdx.z;
    const int n0 = blockIdx.x * 128;
    const int j0 = blockIdx.y * 32;
    const int t  = threadIdx.x;
    const int tx = t & 31;
    const int ty = t >> 5;

    __shared__ float As[32][128];
    __shared__ float Bs[32][32];

    float acc[4][4];
#pragma unroll
    for (int i = 0; i < 4; i++)
#pragma unroll
        for (int u = 0; u < 4; u++) acc[i][u] = 0.f;

    const float* Xb = X + b * CC * NN;

    for (int c0 = 0; c0 < CC; c0 += 32) {
#pragma unroll
        for (int i = 0; i < 4; i++) {
            int idx = t + 256 * i;
            int cc  = idx >> 5;
            int nn  = (idx & 31) * 4;
            float4 v = *(const float4*)(Xb + (c0 + cc) * NN + n0 + nn);
            *(float4*)&As[cc][nn] = v;
        }
        {
            int jj = t >> 3;
            int c4 = (t & 7) * 4;
            float4 wv = *(const float4*)(W + (j0 + jj) * CC + c0 + c4);
            *(float4*)&Bs[jj][c4] = wv;
        }
        __syncthreads();

#pragma unroll
        for (int cc = 0; cc < 32; cc++) {
            float4 a = *(const float4*)&As[cc][tx * 4];
            float b0 = Bs[ty * 4 + 0][cc];
            float b1 = Bs[ty * 4 + 1][cc];
            float b2 = Bs[ty * 4 + 2][cc];
            float b3 = Bs[ty * 4 + 3][cc];
            acc[0][0] += a.x * b0; acc[0][1] += a.x * b1; acc[0][2] += a.x * b2; acc[0][3] += a.x * b3;
            acc[1][0] += a.y * b0; acc[1][1] += a.y * b1; acc[1][2] += a.y * b2; acc[1][3] += a.y * b3;
            acc[2][0] += a.z * b0; acc[2][1] += a.z * b1; acc[2][2] += a.z * b2; acc[2][3] += a.z * b3;
            acc[3][0] += a.w * b0; acc[3][1] += a.w * b1; acc[3][2] += a.w * b2; acc[3][3] += a.w * b3;
        }
        __syncthreads();
    }

    float bj0 = bias[j0 + ty * 4 + 0];
    float bj1 = bias[j0 + ty * 4 + 1];
    float bj2 = bias[j0 + ty * 4 + 2];
    float bj3 = bias[j0 + ty * 4 + 3];
#pragma unroll
    for (int i = 0; i < 4; i++) {
        float4 r;
        r.x = acc[i][0] + bj0;
        r.y = acc[i][1] + bj1;
        r.z = acc[i][2] + bj2;
        r.w = acc[i][3] + bj3;
        if (vtf32) {
            r.x = __uint_as_float(f2tf32(r.x));
            r.y = __uint_as_float(f2tf32(r.y));
            r.z = __uint_as_float(f2tf32(r.z));
            r.w = __uint_as_float(f2tf32(r.w));
        }
        int n = n0 + tx * 4 + i;
        *(float4*)(out + (b * NN + n) * dout + j0 + ty * 4) = r;
    }
}

// ---------------------------------------------------------------------------
// Flash attention, all-tensor + V register pipelining:
//   S = QK^T via split-tf32 3-pass mma (qh in regs, qlo in smem).
//   P = exp(S) on C-fragments, row sums per-thread, reduced once.
//   PV via tf32 mma; V fragments LDG'd from gmem (pre-rounded tf32),
//   double-buffered in registers (load ks+1 while mma ks).
// CTA: 64 queries, 256 threads (8 warps).
// smem: Kh0/Kl0/Kh1/Kl1[32*72] Ps0/Ps1[64*68] lsum[128] Qlo[64*36] (~81.4 KB)
// ---------------------------------------------------------------------------
#define SMEM_FLOATS (4*32*KSTR + 2*64*PSTR + 128 + 64*QLSTR)

__global__ __launch_bounds__(256, 2) void flash_kernel(float* __restrict__ out)
{
    extern __shared__ float sm[];
    uint32_t* Kh0  = (uint32_t*)sm;                 // [d][m] tf32-hi
    uint32_t* Kl0  = Kh0 + 32 * KSTR;               // [d][m] tf32-lo
    uint32_t* Kh1  = Kl0 + 32 * KSTR;
    uint32_t* Kl1  = Kh1 + 32 * KSTR;
    uint32_t* Ps0  = Kl1 + 32 * KSTR;               // [r][m] tf32 P
    uint32_t* Ps1  = Ps0 + 64 * PSTR;
    float*    lsum = (float*)(Ps1 + 64 * PSTR);     // [2][64]
    uint32_t* Qlo  = (uint32_t*)(lsum + 128);       // [r][d] tf32 q-lo

    const int b    = blockIdx.y;
    const int n0   = blockIdx.x * 64;
    const int t    = threadIdx.x;
    const int w    = t >> 5;
    const int lane = t & 31;
    const int gid  = lane >> 2;
    const int tid  = lane & 3;
    // S mapping
    const int ms = (w & 3) * 16;
    const int nh = (w >> 2) * 32;
    // PV mapping
    const int cbase = w * 32;

    const float* gq_b = g_q + (size_t)b * NN * DQK;
    const float* gk_b = g_k + (size_t)b * NN * DQK;
    const float* gv_b = g_v + (size_t)b * NN * CC;
    const float* gv_w = gv_b + tid * CC + cbase + gid;   // warp V base

    // K staging indexing
    const int km0 = t >> 3;              // 0..31
    const int km1 = km0 + 32;            // 32..63
    const int kd4 = (t & 7) * 4;

    // --- Q fragments: qhi in regs; qlo to smem (written by warps 0-3) ---
    uint32_t qhi[4][4];
    {
        const float* q0 = gq_b + (size_t)(n0 + ms + gid) * DQK;
        const float* q1 = q0 + 8 * DQK;
#pragma unroll
        for (int kk = 0; kk < 4; kk++) {
            float v0 = __ldg(q0 + kk * 8 + tid);
            float v1 = __ldg(q1 + kk * 8 + tid);
            float v2 = __ldg(q0 + kk * 8 + tid + 4);
            float v3 = __ldg(q1 + kk * 8 + tid + 4);
            qhi[kk][0] = f2tf32(v0);
            qhi[kk][1] = f2tf32(v1);
            qhi[kk][2] = f2tf32(v2);
            qhi[kk][3] = f2tf32(v3);
            if (w < 4) {
                Qlo[(ms + gid)     * QLSTR + kk * 8 + tid]     = f2tf32(v0 - __uint_as_float(qhi[kk][0]));
                Qlo[(ms + gid + 8) * QLSTR + kk * 8 + tid]     = f2tf32(v1 - __uint_as_float(qhi[kk][1]));
                Qlo[(ms + gid)     * QLSTR + kk * 8 + tid + 4] = f2tf32(v2 - __uint_as_float(qhi[kk][2]));
                Qlo[(ms + gid + 8) * QLSTR + kk * 8 + tid + 4] = f2tf32(v3 - __uint_as_float(qhi[kk][3]));
            }
        }
    }

    float acc[4][4][4];
#pragma unroll
    for (int it = 0; it < 4; it++)
#pragma unroll
        for (int jt = 0; jt < 4; jt++)
#pragma unroll
            for (int u = 0; u < 4; u++) acc[it][jt][u] = 0.f;

    float lrun_lo = 0.f, lrun_hi = 0.f;

    // --- K staging ---
    auto stage_k = [&](const float* gk_t, uint32_t* Kh, uint32_t* Kl) {
        float4 ka = __ldg((const float4*)(gk_t + km0 * DQK + kd4));
        float4 kb = __ldg((const float4*)(gk_t + km1 * DQK + kd4));
        const float* va = (const float*)&ka;
        const float* vb = (const float*)&kb;
#pragma unroll
        for (int i = 0; i < 4; i++) {
            uint32_t h0 = f2tf32(va[i]);
            uint32_t l0 = f2tf32(va[i] - __uint_as_float(h0));
            uint32_t h1 = f2tf32(vb[i]);
            uint32_t l1 = f2tf32(vb[i] - __uint_as_float(h1));
            Kh[(kd4 + i) * KSTR + km0] = h0;
            Kl[(kd4 + i) * KSTR + km0] = l0;
            Kh[(kd4 + i) * KSTR + km1] = h1;
            Kl[(kd4 + i) * KSTR + km1] = l1;
        }
    };

    // --- S phase: 3-pass split-tf32 mma; qlo from smem ---
    auto s_phase = [&](const uint32_t* Kh, const uint32_t* Kl, uint32_t* Pw) {
        float sf[4][4];
#pragma unroll
        for (int j = 0; j < 4; j++)
#pragma unroll
            for (int u = 0; u < 4; u++) sf[j][u] = 0.f;

#pragma unroll
        for (int kk = 0; kk < 4; kk++) {
            const int rb0 = (kk * 8 + tid) * KSTR;
            const int rb1 = (kk * 8 + tid + 4) * KSTR;
            uint32_t ql0 = Qlo[(ms + gid)     * QLSTR + kk * 8 + tid];
            uint32_t ql1 = Qlo[(ms + gid + 8) * QLSTR + kk * 8 + tid];
            uint32_t ql2 = Qlo[(ms + gid)     * QLSTR + kk * 8 + tid + 4];
            uint32_t ql3 = Qlo[(ms + gid + 8) * QLSTR + kk * 8 + tid + 4];
#pragma unroll
            for (int j = 0; j < 4; j++) {
                const int cn = nh + 8 * j + gid;
                uint32_t bh0 = Kh[rb0 + cn];
                uint32_t bh1 = Kh[rb1 + cn];
                uint32_t bl0 = Kl[rb0 + cn];
                uint32_t bl1 = Kl[rb1 + cn];
                mma_tf32(sf[j], qhi[kk][0], qhi[kk][1], qhi[kk][2], qhi[kk][3], bh0, bh1);
                mma_tf32(sf[j], ql0, ql1, ql2, ql3, bh0, bh1);
                mma_tf32(sf[j], qhi[kk][0], qhi[kk][1], qhi[kk][2], qhi[kk][3], bl0, bl1);
            }
        }

#pragma unroll
        for (int j = 0; j < 4; j++) {
            float e0 = __expf(sf[j][0]);
            float e1 = __expf(sf[j][1]);
            float e2 = __expf(sf[j][2]);
            float e3 = __expf(sf[j][3]);
            lrun_lo += e0 + e1;
            lrun_hi += e2 + e3;
            uint2 plo, phi;
            plo.x = f2tf32(e0); plo.y = f2tf32(e1);
            phi.x = f2tf32(e2); phi.y = f2tf32(e3);
            const int cw = nh + 8 * j + 2 * tid;
            *(uint2*)&Pw[(ms + gid)     * PSTR + cw] = plo;
            *(uint2*)&Pw[(ms + gid + 8) * PSTR + cw] = phi;
        }
    };

    // Prologue
    stage_k(gk_b, Kh0, Kl0);
    __syncthreads();
    s_phase(Kh0, Kl0, Ps0);
    stage_k(gk_b + KT * DQK, Kh1, Kl1);

    // Preload V block0 of tile 0 (pre-rounded tf32 bits)
    uint32_t vcur[8];
#pragma unroll
    for (int jt = 0; jt < 4; jt++) {
        vcur[jt]     = __float_as_uint(__ldg(gv_w + jt * 8));
        vcur[4 + jt] = __float_as_uint(__ldg(gv_w + 4 * CC + jt * 8));
    }
    __syncthreads();

    uint32_t* Pc = Ps0;  uint32_t* Pn = Ps1;
    uint32_t* Khc = Kh1; uint32_t* Klc = Kl1;
    uint32_t* Khw = Kh0; uint32_t* Klw = Kl0;

    for (int kt = 0; kt < NKT; kt++) {
        const bool more = (kt + 1 < NKT);
        const bool dok  = (kt + 2 < NKT);

        // K(kt+2): LDG now, split+STS after PV
        float4 ka, kb;
        if (dok) {
            const float* gk_t = gk_b + (size_t)(kt + 2) * KT * DQK;
            ka = __ldg((const float4*)(gk_t + km0 * DQK + kd4));
            kb = __ldg((const float4*)(gk_t + km1 * DQK + kd4));
        }

        // --- PV(kt): register-pipelined V fragments ---
        {
            const float* vb = gv_w + (size_t)(kt * KT) * CC;
#pragma unroll
            for (int ks = 0; ks < 8; ks++) {
                uint32_t vnxt[8];
                if (ks < 7) {
                    const float* vn = vb + (ks + 1) * 8 * CC;
#pragma unroll
                    for (int jt = 0; jt < 4; jt++) {
                        vnxt[jt]     = __float_as_uint(__ldg(vn + jt * 8));
                        vnxt[4 + jt] = __float_as_uint(__ldg(vn + 4 * CC + jt * 8));
                    }
                }
                const int m0 = ks * 8;
#pragma unroll
                for (int it = 0; it < 4; it++) {
                    uint32_t a0 = Pc[(it * 16 + gid)     * PSTR + m0 + tid];
                    uint32_t a1 = Pc[(it * 16 + gid + 8) * PSTR + m0 + tid];
                    uint32_t a2 = Pc[(it * 16 + gid)     * PSTR + m0 + tid + 4];
                    uint32_t a3 = Pc[(it * 16 + gid + 8) * PSTR + m0 + tid + 4];
#pragma unroll
                    for (int jt = 0; jt < 4; jt++)
                        mma_tf32(acc[it][jt], a0, a1, a2, a3, vcur[jt], vcur[4 + jt]);
                }
                if (ks < 7) {
#pragma unroll
                    for (int i = 0; i < 8; i++) vcur[i] = vnxt[i];
                }
            }
        }

        // Stage K(kt+2)
        if (dok) {
            const float* va = (const float*)&ka;
            const float* vb2 = (const float*)&kb;
#pragma unroll
            for (int i = 0; i < 4; i++) {
                uint32_t h0 = f2tf32(va[i]);
                uint32_t l0 = f2tf32(va[i] - __uint_as_float(h0));
                uint32_t h1 = f2tf32(vb2[i]);
                uint32_t l1 = f2tf32(vb2[i] - __uint_as_float(h1));
                Khw[(kd4 + i) * KSTR + km0] = h0;
                Klw[(kd4 + i) * KSTR + km0] = l0;
                Khw[(kd4 + i) * KSTR + km1] = h1;
                Klw[(kd4 + i) * KSTR + km1] = l1;
            }
        }

        // --- S(kt+1) -> Pn, then preload V block0 of tile kt+1 ---
        if (more) {
            s_phase(Khc, Klc, Pn);
            const float* vn = gv_w + (size_t)((kt + 1) * KT) * CC;
#pragma unroll
            for (int jt = 0; jt < 4; jt++) {
                vcur[jt]     = __float_as_uint(__ldg(vn + jt * 8));
                vcur[4 + jt] = __float_as_uint(__ldg(vn + 4 * CC + jt * 8));
            }
        }
        __syncthreads();

        uint32_t* pt;
        pt = Pc;  Pc  = Pn;  Pn  = pt;
        pt = Khc; Khc = Khw; Khw = pt;
        pt = Klc; Klc = Klw; Klw = pt;
    }

    // --- final row-sum reduction ---
    lrun_lo += __shfl_xor_sync(0xffffffffu, lrun_lo, 1);
    lrun_lo += __shfl_xor_sync(0xffffffffu, lrun_lo, 2);
    lrun_hi += __shfl_xor_sync(0xffffffffu, lrun_hi, 1);
    lrun_hi += __shfl_xor_sync(0xffffffffu, lrun_hi, 2);
    if (tid == 0) {
        lsum[(w >> 2) * 64 + ms + gid]     = lrun_lo;
        lsum[(w >> 2) * 64 + ms + gid + 8] = lrun_hi;
    }
    __syncthreads();

    // --- direct STG epilogue: out[b][c][n0+r] ---
    float* ob = out + (size_t)b * CC * NN + n0;
#pragma unroll
    for (int it = 0; it < 4; it++) {
        const int r_lo = it * 16 + gid;
        const int r_hi = r_lo + 8;
        const float ilo = 1.f / (lsum[r_lo] + lsum[64 + r_lo]);
        const float ihi = 1.f / (lsum[r_hi] + lsum[64 + r_hi]);
#pragma unroll
        for (int jt = 0; jt < 4; jt++) {
            const int c0 = cbase + jt * 8 + tid * 2;
            ob[(size_t)(c0    ) * NN + r_lo] = acc[it][jt][0] * ilo;
            ob[(size_t)(c0 + 1) * NN + r_lo] = acc[it][jt][1] * ilo;
            ob[(size_t)(c0    ) * NN + r_hi] = acc[it][jt][2] * ihi;
            ob[(size_t)(c0 + 1) * NN + r_hi] = acc[it][jt][3] * ihi;
        }
    }
}

// ---------------------------------------------------------------------------
extern "C" void kernel_launch(void* const* d_in, const int* in_sizes, int n_in,
                              void* d_out, int out_size)
{
    const float* f1 = (const float*)d_in[0];
    const float* f2 = (const float*)d_in[1];
    const float* Wq = (const float*)d_in[2];
    const float* bq = (const float*)d_in[3];
    const float* Wk = (const float*)d_in[4];
    const float* bk = (const float*)d_in[5];
    const float* Wv = (const float*)d_in[6];
    const float* bv = (const float*)d_in[7];
    float* out = (float*)d_out;

    float *qp, *kp, *vp;
    cudaGetSymbolAddress((void**)&qp, g_q);
    cudaGetSymbolAddress((void**)&kp, g_k);
    cudaGetSymbolAddress((void**)&vp, g_v);

    const int smem_bytes = SMEM_FLOATS * (int)sizeof(float);
    cudaFuncSetAttribute(flash_kernel,
                         cudaFuncAttributeMaxDynamicSharedMemorySize, smem_bytes);

    proj_kernel<<<dim3(NN / 128, 1, BB), 256>>>(f1, Wq, bq, qp, DQK, 0);
    proj_kernel<<<dim3(NN / 128, 1, BB), 256>>>(f2, Wk, bk, kp, DQK, 0);
    proj_kernel<<<dim3(NN / 128, 8, BB), 256>>>(f2, Wv, bv, vp, CC, 1);
    flash_kernel<<<dim3(NN / 64, BB), 256, smem_bytes>>>(out);
}